// round 16
// baseline (speedup 1.0000x reference)
// R16: attn 64q/256thr with sO overlaid on sK (2 CTAs/SM) + single-barrier hgemm.
#include <cuda_runtime.h>
#include <cuda_fp16.h>
#include <math.h>
#include <cstdint>

#define B_    32
#define N_    3136
#define DIM_  320
#define CN_   400
#define HEADS_ 5
#define NK_   196
#define DQ_   80
#define DV_   64
#define AQ_   64

// ---------------- scratch (static device globals; no runtime allocation) ----
__device__ __align__(16) __half g_xh[B_ * N_  * DIM_];
__device__ __align__(16) __half g_dw[B_ * NK_ * DIM_];
__device__ __align__(16) float  g_pre[B_ * NK_ * CN_];
__device__ __align__(16) __half g_xs[B_ * NK_ * CN_];
__device__ __align__(16) __half g_q [B_ * N_  * CN_];
__device__ __align__(16) __half g_kv[B_ * NK_ * 720];
__device__ __align__(16) __half g_av[B_ * N_  * DIM_];
__device__ __align__(16) __half g_wtq[CN_ * DIM_];
__device__ __align__(16) __half g_wtkv[720 * CN_];
__device__ __align__(16) __half g_wtp[DIM_ * DIM_];
__device__ __align__(16) __half g_wpw[CN_ * DIM_];

// ---------------- helpers ----------------------------------------------------
__device__ __forceinline__ uint32_t smem_u32(const void* p) {
    uint32_t a;
    asm("{ .reg .u64 t; cvta.to.shared.u64 t, %1; cvt.u32.u64 %0, t; }"
        : "=r"(a) : "l"(p));
    return a;
}
#define CPA(dst, src, sz) \
    asm volatile("cp.async.cg.shared.global [%0], [%1], 16, %2;" \
        :: "r"(dst), "l"(src), "r"(sz))
#define CPC() asm volatile("cp.async.commit_group;" ::: "memory")
#define CPW(n) asm volatile("cp.async.wait_group %0;" :: "n"(n) : "memory")

__device__ __forceinline__ void ldsm4(uint32_t r[4], uint32_t a) {
    asm volatile("ldmatrix.sync.aligned.m8n8.x4.shared.b16 {%0,%1,%2,%3}, [%4];"
        : "=r"(r[0]), "=r"(r[1]), "=r"(r[2]), "=r"(r[3]) : "r"(a));
}
__device__ __forceinline__ void ldsm2(uint32_t r[2], uint32_t a) {
    asm volatile("ldmatrix.sync.aligned.m8n8.x2.shared.b16 {%0,%1}, [%2];"
        : "=r"(r[0]), "=r"(r[1]) : "r"(a));
}
__device__ __forceinline__ void ldsm1(uint32_t& r, uint32_t a) {
    asm volatile("ldmatrix.sync.aligned.m8n8.x1.shared.b16 {%0}, [%1];"
        : "=r"(r) : "r"(a));
}
__device__ __forceinline__ void ldsm4t(uint32_t r[4], uint32_t a) {
    asm volatile("ldmatrix.sync.aligned.m8n8.x4.trans.shared.b16 {%0,%1,%2,%3}, [%4];"
        : "=r"(r[0]), "=r"(r[1]), "=r"(r[2]), "=r"(r[3]) : "r"(a));
}

__device__ __forceinline__ void mma16(float c[4],
                                      uint32_t a0, uint32_t a1, uint32_t a2, uint32_t a3,
                                      uint32_t b0, uint32_t b1) {
    asm volatile(
        "mma.sync.aligned.m16n8k16.row.col.f32.f16.f16.f32 "
        "{%0,%1,%2,%3}, {%4,%5,%6,%7}, {%8,%9}, {%0,%1,%2,%3};"
        : "+f"(c[0]), "+f"(c[1]), "+f"(c[2]), "+f"(c[3])
        : "r"(a0), "r"(a1), "r"(a2), "r"(a3), "r"(b0), "r"(b1));
}
__device__ __forceinline__ void mma8k(float c[4], uint32_t a0, uint32_t a1, uint32_t b0) {
    asm volatile(
        "mma.sync.aligned.m16n8k8.row.col.f32.f16.f16.f32 "
        "{%0,%1,%2,%3}, {%4,%5}, {%6}, {%0,%1,%2,%3};"
        : "+f"(c[0]), "+f"(c[1]), "+f"(c[2]), "+f"(c[3])
        : "r"(a0), "r"(a1), "r"(b0));
}
__device__ __forceinline__ uint32_t packh2(float a, float b) {
    __half2 h = __floats2half2_rn(a, b);
    return *reinterpret_cast<uint32_t*>(&h);
}
__inline__ __device__ float warp_sum(float v) {
#pragma unroll
    for (int o = 16; o; o >>= 1) v += __shfl_xor_sync(0xffffffffu, v, o);
    return v;
}

// ---------------- dwconv + x->fp16 (single fused pass over x) ----------------
__global__ __launch_bounds__(256) void dwcvt_kernel(
    const float* __restrict__ x, const float* __restrict__ dww,
    const float* __restrict__ dwb)
{
    int b  = blockIdx.x / NK_;
    int p  = blockIdx.x % NK_;
    int oh = p / 14, ow = p % 14;
    __shared__ float sp[16 * DIM_];

    int tid = threadIdx.x;
    const float* xb = x + (size_t)b * N_ * DIM_;
    __half* xhb = g_xh + (size_t)b * N_ * DIM_;
    for (int idx = tid; idx < 16 * DIM_; idx += 256) {
        int i = idx / DIM_, c = idx - i * DIM_;
        int n = (oh * 4 + (i >> 2)) * 56 + (ow * 4 + (i & 3));
        float v = xb[(size_t)n * DIM_ + c];
        sp[i * DIM_ + c] = v;
        xhb[(size_t)n * DIM_ + c] = __float2half_rn(v);
    }
    __syncthreads();
    for (int c = tid; c < DIM_; c += 256) {
        float acc = dwb[c];
#pragma unroll
        for (int i = 0; i < 16; i++)
            acc = fmaf(sp[i * DIM_ + c], dww[c * 16 + i], acc);
        g_dw[(size_t)blockIdx.x * DIM_ + c] = __float2half_rn(acc);
    }
}

// ---------------- weight prep ------------------------------------------------
__global__ void transpose_all(const float* __restrict__ qw, const float* __restrict__ kw,
                              const float* __restrict__ vw, const float* __restrict__ pjw,
                              const float* __restrict__ pww)
{
    int k = blockIdx.x * 256 + threadIdx.x;
    int n = blockIdx.y;
    int which = blockIdx.z;
    if (which == 0) {
        if (k < DIM_ && n < CN_) g_wtq[(size_t)n * DIM_ + k] = __float2half_rn(qw[(size_t)k * CN_ + n]);
    } else if (which == 1) {
        if (k < CN_ && n < CN_)  g_wtkv[(size_t)n * CN_ + k] = __float2half_rn(kw[(size_t)k * CN_ + n]);
    } else if (which == 2) {
        if (k < CN_ && n < DIM_) g_wtkv[(size_t)(400 + n) * CN_ + k] = __float2half_rn(vw[(size_t)k * DIM_ + n]);
    } else if (which == 3) {
        if (k < DIM_ && n < DIM_) g_wtp[(size_t)n * DIM_ + k] = __float2half_rn(pjw[(size_t)k * DIM_ + n]);
    } else {
        if (k < DIM_ && n < CN_) g_wpw[(size_t)n * DIM_ + k] = __float2half_rn(pww[(size_t)n * DIM_ + k]);
    }
}

// ---------------- LN + GELU: g_pre -> g_xs -----------------------------------
__global__ __launch_bounds__(128) void lngelu_kernel(
    const float* __restrict__ lng, const float* __restrict__ lnb)
{
    __shared__ float r1[4], r2[4];
    int r = blockIdx.x, tid = threadIdx.x, lane = tid & 31, w = tid >> 5;
    const float* row = g_pre + (size_t)r * CN_;
    float v[4];
    float s1 = 0.f, s2 = 0.f;
#pragma unroll
    for (int i = 0; i < 4; i++) {
        int c = tid + i * 128;
        v[i] = (c < CN_) ? row[c] : 0.f;
        s1 += v[i]; s2 += v[i] * v[i];
    }
    s1 = warp_sum(s1); s2 = warp_sum(s2);
    if (lane == 0) { r1[w] = s1; r2[w] = s2; }
    __syncthreads();
    float a = r1[0] + r1[1] + r1[2] + r1[3];
    float bq = r2[0] + r2[1] + r2[2] + r2[3];
    float mu = a / (float)CN_;
    float rstd = rsqrtf(bq / (float)CN_ - mu * mu + 1e-5f);
#pragma unroll
    for (int i = 0; i < 4; i++) {
        int c = tid + i * 128;
        if (c < CN_) {
            float y = (v[i] - mu) * rstd * lng[c] + lnb[c];
            float g = 0.5f * y * (1.f + erff(y * 0.70710678118654752f));
            g_xs[(size_t)r * CN_ + c] = __float2half_rn(g);
        }
    }
}

// ---------------- fp16 HMMA GEMM: BM=128, BN=80, BK=64, 3-stage, 1 barrier ---
#define HSTR 72
#define ATILE (128 * HSTR)
#define BTILE (80 * HSTR)
#define STAGEB ((ATILE + BTILE) * 2)
__global__ __launch_bounds__(256, 2) void hgemm(
    const __half* __restrict__ A, const __half* __restrict__ Bt,
    const float* __restrict__ bias, float* __restrict__ Cf,
    __half* __restrict__ Ch, int M, int N, int K)
{
    extern __shared__ __half hsm[];
    uint32_t sbase = smem_u32(hsm);

    int tid = threadIdx.x;
    int lane = tid & 31, w = tid >> 5;
    int g = lane >> 2, t = lane & 3;
    int lrow = lane & 15, lkh = lane >> 4;
    int row0 = blockIdx.x * 128, n0 = blockIdx.y * 80;
    int wm = (w & 3) * 32, wn = (w >> 2) * 40;
    int nIter = (K + 63) / 64;

    float acc[2][5][4] = {};

    auto load_stage = [&](int s, int k0) {
        uint32_t base = sbase + s * STAGEB;
#pragma unroll
        for (int it = 0; it < 4; it++) {
            int gr = tid + it * 256;
            int r = gr >> 3, c8 = (gr & 7) << 3;
            int kk = k0 + c8;
            const __half* sa = A + (size_t)(row0 + r) * K + (kk < K ? kk : 0);
            CPA(base + (r * HSTR + c8) * 2, sa, (kk < K) ? 16 : 0);
        }
#pragma unroll
        for (int it = 0; it < 3; it++) {
            int gr = tid + it * 256;
            if (gr < 640) {
                int r = gr >> 3, c8 = (gr & 7) << 3;
                int kk = k0 + c8;
                const __half* sb = Bt + (size_t)(n0 + r) * K + (kk < K ? kk : 0);
                CPA(base + ATILE * 2 + (r * HSTR + c8) * 2, sb, (kk < K) ? 16 : 0);
            }
        }
        CPC();
    };

    load_stage(0, 0);
    if (nIter > 1) load_stage(1, 64);
    for (int i = 0; i < nIter; i++) {
        if (i + 1 < nIter) CPW(1);
        else CPW(0);
        __syncthreads();   // stage i ready AND all warps done with compute(i-1)

        uint32_t sbA = sbase + (i % 3) * STAGEB;
        uint32_t sbB = sbA + ATILE * 2;
#pragma unroll
        for (int ks = 0; ks < 4; ks++) {
            uint32_t af[2][4], q0[4], q1[4], e2[2];
#pragma unroll
            for (int mi = 0; mi < 2; mi++)
                ldsm4(af[mi], sbA + ((wm + mi * 16 + lrow) * HSTR + ks * 16 + lkh * 8) * 2);
            ldsm4(q0, sbB + ((wn + lane) * HSTR + ks * 16 + 0) * 2);
            ldsm4(q1, sbB + ((wn + lane) * HSTR + ks * 16 + 8) * 2);
            ldsm2(e2, sbB + ((wn + 32 + (lane & 7)) * HSTR + ks * 16 + ((lane >> 3) & 1) * 8) * 2);
#pragma unroll
            for (int mi = 0; mi < 2; mi++) {
#pragma unroll
                for (int nj = 0; nj < 4; nj++)
                    mma16(acc[mi][nj], af[mi][0], af[mi][1], af[mi][2], af[mi][3],
                          q0[nj], q1[nj]);
                mma16(acc[mi][4], af[mi][0], af[mi][1], af[mi][2], af[mi][3],
                      e2[0], e2[1]);
            }
        }
        // issue loads for stage i+2 AFTER compute: barrier above guarantees no
        // warp is still reading buffer (i+2)%3 == (i-1)%3.
        if (i + 2 < nIter) load_stage((i + 2) % 3, (i + 2) * 64);
    }

#pragma unroll
    for (int mi = 0; mi < 2; mi++)
#pragma unroll
        for (int nj = 0; nj < 5; nj++) {
            int r = row0 + wm + mi * 16 + g;
            int c = n0 + wn + nj * 8 + 2 * t;
            if (Ch) {
                *reinterpret_cast<__half2*>(Ch + (size_t)r * N + c) =
                    __floats2half2_rn(acc[mi][nj][0], acc[mi][nj][1]);
                *reinterpret_cast<__half2*>(Ch + (size_t)(r + 8) * N + c) =
                    __floats2half2_rn(acc[mi][nj][2], acc[mi][nj][3]);
            } else {
                float b0 = bias ? bias[c]     : 0.f;
                float b1 = bias ? bias[c + 1] : 0.f;
                *reinterpret_cast<float2*>(Cf + (size_t)r * N + c) =
                    make_float2(acc[mi][nj][0] + b0, acc[mi][nj][1] + b1);
                *reinterpret_cast<float2*>(Cf + (size_t)(r + 8) * N + c) =
                    make_float2(acc[mi][nj][2] + b0, acc[mi][nj][3] + b1);
            }
        }
}

// ---------------- fused attention: 64q, 256 thr, sO overlaid on sK -----------
// halves layout: sQ[64][88]=5632, sK[224][88]=19712, sV[224][72]=16128
// sO (f32 [64][68] = 17408 B) overlays sK after phase 1.
// f32 extras at OF32: pmax[256], psum[256], srcp[64].
#define SQST 88
#define SKST 88
#define SVST 72
#define SOST 68
#define OQ   0
#define OK_  5632
#define OV   25344
#define OF32 41472
#define ATTN_SMEM (OF32 * 2 + (256 + 256 + 64) * 4)   // 85248 B -> 2 CTAs/SM
__global__ __launch_bounds__(256, 2) void attn_kernel(float scale)
{
    extern __shared__ __half hs[];
    float* sO   = reinterpret_cast<float*>(hs + OK_);   // valid after phase 1
    float* pmax = reinterpret_cast<float*>(hs + OF32);
    float* psum = pmax + 256;
    float* srcp = psum + 256;

    int qt = blockIdx.x, h = blockIdx.y, b = blockIdx.z;
    int q0 = qt * AQ_;
    int tid = threadIdx.x;
    int lane = tid & 31, w = tid >> 5;
    int g = lane >> 2, t = lane & 3;
    int lrow = lane & 15, lkh = lane >> 4;
    int rg = w & 1, wg = w >> 1;
    int mp = rg * 32, nqk = wg * 56;

    {
        const __half* qb = g_q + ((size_t)(b * N_) + q0) * CN_ + h * DQ_;
        for (int idx = tid; idx < AQ_ * 10; idx += 256) {
            int r = idx / 10, c8 = (idx % 10) * 8;
            *reinterpret_cast<uint4*>(hs + OQ + r * SQST + c8) =
                *reinterpret_cast<const uint4*>(qb + (size_t)r * CN_ + c8);
        }
        const __half* kb = g_kv + (size_t)b * NK_ * 720 + h * DQ_;
        for (int idx = tid; idx < 224 * 10; idx += 256) {
            int j = idx / 10, c8 = (idx % 10) * 8;
            uint4 v = make_uint4(0, 0, 0, 0);
            if (j < NK_) v = *reinterpret_cast<const uint4*>(kb + (size_t)j * 720 + c8);
            *reinterpret_cast<uint4*>(hs + OK_ + j * SKST + c8) = v;
        }
        const __half* vb = g_kv + (size_t)b * NK_ * 720 + 400 + h * DV_;
        for (int idx = tid; idx < 224 * 8; idx += 256) {
            int j = idx / 8, c8 = (idx % 8) * 8;
            uint4 v = make_uint4(0, 0, 0, 0);
            if (j < NK_) v = *reinterpret_cast<const uint4*>(vb + (size_t)j * 720 + c8);
            *reinterpret_cast<uint4*>(hs + OV + j * SVST + c8) = v;
        }
    }
    __syncthreads();

    // Phase 1: S = Q @ K^T.  warp: rows mp..mp+31, keys nqk..nqk+55
    float acc[2][7][4] = {};
    {
        uint32_t sQb = smem_u32(hs + OQ);
        uint32_t sKb = smem_u32(hs + OK_);
#pragma unroll
        for (int ks = 0; ks < 5; ks++) {
            uint32_t af[2][4];
#pragma unroll
            for (int mi = 0; mi < 2; mi++)
                ldsm4(af[mi], sQb + ((mp + mi * 16 + lrow) * SQST + ks * 16 + lkh * 8) * 2);
            uint32_t bf[7][2];
#pragma unroll
            for (int kh = 0; kh < 2; kh++) {
                uint32_t b4[4], b2[2], b1;
                ldsm4(b4, sKb + ((nqk + lane) * SKST + ks * 16 + kh * 8) * 2);
                ldsm2(b2, sKb + ((nqk + 32 + (lane & 15)) * SKST + ks * 16 + kh * 8) * 2);
                ldsm1(b1, sKb + ((nqk + 48 + (lane & 7)) * SKST + ks * 16 + kh * 8) * 2);
                bf[0][kh] = b4[0]; bf[1][kh] = b4[1]; bf[2][kh] = b4[2]; bf[3][kh] = b4[3];
                bf[4][kh] = b2[0]; bf[5][kh] = b2[1]; bf[6][kh] = b1;
            }
#pragma unroll
            for (int mi = 0; mi < 2; mi++)
#pragma unroll
                for (int nj = 0; nj < 7; nj++)
                    mma16(acc[mi][nj], af[mi][0], af[mi][1], af[mi][2], af[mi][3],
                          bf[nj][0], bf[nj][1]);
        }
    }

    // partial max per warp group
#pragma unroll
    for (int mi = 0; mi < 2; mi++) {
        float ma = -1e30f, mb = -1e30f;
#pragma unroll
        for (int nj = 0; nj < 7; nj++) {
            int c = nqk + nj * 8 + 2 * t;
            if (c < NK_) {
                ma = fmaxf(ma, fmaxf(acc[mi][nj][0], acc[mi][nj][1]) * scale);
                mb = fmaxf(mb, fmaxf(acc[mi][nj][2], acc[mi][nj][3]) * scale);
            }
        }
#pragma unroll
        for (int o = 1; o <= 2; o <<= 1) {
            ma = fmaxf(ma, __shfl_xor_sync(0xffffffffu, ma, o));
            mb = fmaxf(mb, __shfl_xor_sync(0xffffffffu, mb, o));
        }
        if (t == 0) {
            pmax[(mp + mi * 16 + g) * 4 + wg]     = ma;
            pmax[(mp + mi * 16 + 8 + g) * 4 + wg] = mb;
        }
    }
    __syncthreads();   // all phase-1 sK reads + pmax writes complete

    // zero sO (overlays sK) — safe now
    for (int i = tid; i < AQ_ * SOST; i += 256) sO[i] = 0.f;

    // exp + partial sums; probabilities stay in registers
#pragma unroll
    for (int mi = 0; mi < 2; mi++) {
        int rA = mp + mi * 16 + g, rB = rA + 8;
        float ma = fmaxf(fmaxf(pmax[rA * 4], pmax[rA * 4 + 1]),
                         fmaxf(pmax[rA * 4 + 2], pmax[rA * 4 + 3]));
        float mb = fmaxf(fmaxf(pmax[rB * 4], pmax[rB * 4 + 1]),
                         fmaxf(pmax[rB * 4 + 2], pmax[rB * 4 + 3]));
        float sa = 0.f, sb = 0.f;
#pragma unroll
        for (int nj = 0; nj < 7; nj++) {
            int c = nqk + nj * 8 + 2 * t;
            if (c < NK_) {
                float e0 = __expf(acc[mi][nj][0] * scale - ma);
                float e1 = __expf(acc[mi][nj][1] * scale - ma);
                float e2 = __expf(acc[mi][nj][2] * scale - mb);
                float e3 = __expf(acc[mi][nj][3] * scale - mb);
                acc[mi][nj][0] = e0; acc[mi][nj][1] = e1;
                acc[mi][nj][2] = e2; acc[mi][nj][3] = e3;
                sa += e0 + e1; sb += e2 + e3;
            } else {
                acc[mi][nj][0] = acc[mi][nj][1] = 0.f;
                acc[mi][nj][2] = acc[mi][nj][3] = 0.f;
            }
        }
#pragma unroll
        for (int o = 1; o <= 2; o <<= 1) {
            sa += __shfl_xor_sync(0xffffffffu, sa, o);
            sb += __shfl_xor_sync(0xffffffffu, sb, o);
        }
        if (t == 0) { psum[rA * 4 + wg] = sa; psum[rB * 4 + wg] = sb; }
    }

    uint32_t ppa[2][7], ppb[2][7];
#pragma unroll
    for (int mi = 0; mi < 2; mi++)
#pragma unroll
        for (int nj = 0; nj < 7; nj++) {
            ppa[mi][nj] = packh2(acc[mi][nj][0], acc[mi][nj][1]);
            ppb[mi][nj] = packh2(acc[mi][nj][2], acc[mi][nj][3]);
        }
    __syncthreads();   // sO zeros + psum visible

    if (tid < AQ_)
        srcp[tid] = 1.f / (psum[tid * 4] + psum[tid * 4 + 1] +
                           psum[tid * 4 + 2] + psum[tid * 4 + 3]);

    // Phase 3: split-K over this warp's 56 keys; V via ldmatrix.trans
    {
        uint32_t sVb = smem_u32(hs + OV);
#pragma unroll
        for (int vh = 0; vh < 2; vh++) {
            float o[2][4][4] = {};
#pragma unroll
            for (int ks = 0; ks < 7; ks++) {
                uint32_t bt[4];
                ldsm4t(bt, sVb + ((nqk + ks * 8 + (lane & 7)) * SVST
                                  + vh * 32 + (lane >> 3) * 8) * 2);
#pragma unroll
                for (int mi = 0; mi < 2; mi++)
#pragma unroll
                    for (int nj = 0; nj < 4; nj++)
                        mma8k(o[mi][nj], ppa[mi][ks], ppb[mi][ks], bt[nj]);
            }
#pragma unroll
            for (int mi = 0; mi < 2; mi++)
#pragma unroll
                for (int nj = 0; nj < 4; nj++) {
                    int row = mp + mi * 16 + g;
                    int col = vh * 32 + nj * 8 + 2 * t;
                    atomicAdd(&sO[row * SOST + col],           o[mi][nj][0]);
                    atomicAdd(&sO[row * SOST + col + 1],       o[mi][nj][1]);
                    atomicAdd(&sO[(row + 8) * SOST + col],     o[mi][nj][2]);
                    atomicAdd(&sO[(row + 8) * SOST + col + 1], o[mi][nj][3]);
                }
        }
    }
    __syncthreads();

    for (int idx = tid; idx < AQ_ * 32; idx += 256) {
        int r = idx >> 5, c2 = idx & 31;
        float rc = srcp[r];
        float o0 = sO[r * SOST + 2 * c2]     * rc;
        float o1 = sO[r * SOST + 2 * c2 + 1] * rc;
        *reinterpret_cast<__half2*>(
            g_av + ((size_t)(b * N_) + q0 + r) * DIM_ + h * DV_ + 2 * c2) =
            __floats2half2_rn(o0, o1);
    }
}

// ---------------- launch -----------------------------------------------------
extern "C" void kernel_launch(void* const* d_in, const int* in_sizes, int n_in,
                              void* d_out, int out_size)
{
    const float* x   = (const float*)d_in[0];
    const float* dww = (const float*)d_in[3];
    const float* dwb = (const float*)d_in[4];
    const float* pww = (const float*)d_in[5];
    const float* pwb = (const float*)d_in[6];
    const float* lng = (const float*)d_in[7];
    const float* lnb = (const float*)d_in[8];
    const float* qw  = (const float*)d_in[9];
    const float* kw  = (const float*)d_in[10];
    const float* vw  = (const float*)d_in[11];
    const float* pjw = (const float*)d_in[12];
    const float* pjb = (const float*)d_in[13];
    float* out = (float*)d_out;

    __half *pxh, *pdw, *pxs, *pq, *pkv, *pav, *pwtq, *pwtkv, *pwtp, *pwpw;
    float *ppre;
    cudaGetSymbolAddress((void**)&pxh,   g_xh);
    cudaGetSymbolAddress((void**)&pdw,   g_dw);
    cudaGetSymbolAddress((void**)&ppre,  g_pre);
    cudaGetSymbolAddress((void**)&pxs,   g_xs);
    cudaGetSymbolAddress((void**)&pq,    g_q);
    cudaGetSymbolAddress((void**)&pkv,   g_kv);
    cudaGetSymbolAddress((void**)&pav,   g_av);
    cudaGetSymbolAddress((void**)&pwtq,  g_wtq);
    cudaGetSymbolAddress((void**)&pwtkv, g_wtkv);
    cudaGetSymbolAddress((void**)&pwtp,  g_wtp);
    cudaGetSymbolAddress((void**)&pwpw,  g_wpw);

    dwcvt_kernel<<<B_ * NK_, 256>>>(x, dww, dwb);
    transpose_all<<<dim3(2, CN_, 5), 256>>>(qw, kw, vw, pjw, pww);

    const int gemm_smem = 3 * STAGEB;   // 89856 B
    cudaFuncSetAttribute(hgemm, cudaFuncAttributeMaxDynamicSharedMemorySize, gemm_smem);

    // pointwise conv as GEMM
    hgemm<<<dim3(B_ * NK_ / 128, CN_ / 80), 256, gemm_smem>>>(
        pdw, pwpw, pwb, ppre, nullptr, B_ * NK_, CN_, DIM_);

    lngelu_kernel<<<B_ * NK_, 128>>>(lng, lnb);

    // q = x @ q_w
    hgemm<<<dim3(B_ * N_ / 128, CN_ / 80), 256, gemm_smem>>>(
        pxh, pwtq, nullptr, nullptr, pq, B_ * N_, CN_, DIM_);

    // kv = xs @ [k_w | v_w]
    hgemm<<<dim3(B_ * NK_ / 128, 720 / 80), 256, gemm_smem>>>(
        pxs, pwtkv, nullptr, nullptr, pkv, B_ * NK_, 720, CN_);

    cudaFuncSetAttribute(attn_kernel,
                         cudaFuncAttributeMaxDynamicSharedMemorySize, ATTN_SMEM);
    attn_kernel<<<dim3(N_ / AQ_, HEADS_, B_), 256, ATTN_SMEM>>>(
        0.11180339887498949f /* 80^-0.5 */);

    // out = av @ proj_w + proj_b
    hgemm<<<dim3(B_ * N_ / 128, DIM_ / 80), 256, gemm_smem>>>(
        pav, pwtp, pjb, out, nullptr, B_ * N_, DIM_, DIM_);
}

// round 17
// speedup vs baseline: 1.0440x; 1.0440x over previous
// R17: R15 base + corrected single-barrier hgemm (load issued BEFORE compute).
#include <cuda_runtime.h>
#include <cuda_fp16.h>
#include <math.h>
#include <cstdint>

#define B_    32
#define N_    3136
#define DIM_  320
#define CN_   400
#define HEADS_ 5
#define NK_   196
#define DQ_   80
#define DV_   64
#define AQ_   128

// ---------------- scratch (static device globals; no runtime allocation) ----
__device__ __align__(16) __half g_xh[B_ * N_  * DIM_];
__device__ __align__(16) __half g_dw[B_ * NK_ * DIM_];
__device__ __align__(16) float  g_pre[B_ * NK_ * CN_];
__device__ __align__(16) __half g_xs[B_ * NK_ * CN_];
__device__ __align__(16) __half g_q [B_ * N_  * CN_];
__device__ __align__(16) __half g_kv[B_ * NK_ * 720];
__device__ __align__(16) __half g_av[B_ * N_  * DIM_];
__device__ __align__(16) __half g_wtq[CN_ * DIM_];
__device__ __align__(16) __half g_wtkv[720 * CN_];
__device__ __align__(16) __half g_wtp[DIM_ * DIM_];
__device__ __align__(16) __half g_wpw[CN_ * DIM_];

// ---------------- helpers ----------------------------------------------------
__device__ __forceinline__ uint32_t smem_u32(const void* p) {
    uint32_t a;
    asm("{ .reg .u64 t; cvta.to.shared.u64 t, %1; cvt.u32.u64 %0, t; }"
        : "=r"(a) : "l"(p));
    return a;
}
#define CPA(dst, src, sz) \
    asm volatile("cp.async.cg.shared.global [%0], [%1], 16, %2;" \
        :: "r"(dst), "l"(src), "r"(sz))
#define CPC() asm volatile("cp.async.commit_group;" ::: "memory")
#define CPW(n) asm volatile("cp.async.wait_group %0;" :: "n"(n) : "memory")

__device__ __forceinline__ void ldsm4(uint32_t r[4], uint32_t a) {
    asm volatile("ldmatrix.sync.aligned.m8n8.x4.shared.b16 {%0,%1,%2,%3}, [%4];"
        : "=r"(r[0]), "=r"(r[1]), "=r"(r[2]), "=r"(r[3]) : "r"(a));
}
__device__ __forceinline__ void ldsm2(uint32_t r[2], uint32_t a) {
    asm volatile("ldmatrix.sync.aligned.m8n8.x2.shared.b16 {%0,%1}, [%2];"
        : "=r"(r[0]), "=r"(r[1]) : "r"(a));
}
__device__ __forceinline__ void ldsm1(uint32_t& r, uint32_t a) {
    asm volatile("ldmatrix.sync.aligned.m8n8.x1.shared.b16 {%0}, [%1];"
        : "=r"(r) : "r"(a));
}
__device__ __forceinline__ void ldsm4t(uint32_t r[4], uint32_t a) {
    asm volatile("ldmatrix.sync.aligned.m8n8.x4.trans.shared.b16 {%0,%1,%2,%3}, [%4];"
        : "=r"(r[0]), "=r"(r[1]), "=r"(r[2]), "=r"(r[3]) : "r"(a));
}

__device__ __forceinline__ void mma16(float c[4],
                                      uint32_t a0, uint32_t a1, uint32_t a2, uint32_t a3,
                                      uint32_t b0, uint32_t b1) {
    asm volatile(
        "mma.sync.aligned.m16n8k16.row.col.f32.f16.f16.f32 "
        "{%0,%1,%2,%3}, {%4,%5,%6,%7}, {%8,%9}, {%0,%1,%2,%3};"
        : "+f"(c[0]), "+f"(c[1]), "+f"(c[2]), "+f"(c[3])
        : "r"(a0), "r"(a1), "r"(a2), "r"(a3), "r"(b0), "r"(b1));
}
__device__ __forceinline__ void mma8k(float c[4], uint32_t a0, uint32_t a1, uint32_t b0) {
    asm volatile(
        "mma.sync.aligned.m16n8k8.row.col.f32.f16.f16.f32 "
        "{%0,%1,%2,%3}, {%4,%5}, {%6}, {%0,%1,%2,%3};"
        : "+f"(c[0]), "+f"(c[1]), "+f"(c[2]), "+f"(c[3])
        : "r"(a0), "r"(a1), "r"(b0));
}
__device__ __forceinline__ uint32_t packh2(float a, float b) {
    __half2 h = __floats2half2_rn(a, b);
    return *reinterpret_cast<uint32_t*>(&h);
}
__inline__ __device__ float warp_sum(float v) {
#pragma unroll
    for (int o = 16; o; o >>= 1) v += __shfl_xor_sync(0xffffffffu, v, o);
    return v;
}

// ---------------- dwconv + x->fp16 (single fused pass over x) ----------------
__global__ __launch_bounds__(256) void dwcvt_kernel(
    const float* __restrict__ x, const float* __restrict__ dww,
    const float* __restrict__ dwb)
{
    int b  = blockIdx.x / NK_;
    int p  = blockIdx.x % NK_;
    int oh = p / 14, ow = p % 14;
    __shared__ float sp[16 * DIM_];

    int tid = threadIdx.x;
    const float* xb = x + (size_t)b * N_ * DIM_;
    __half* xhb = g_xh + (size_t)b * N_ * DIM_;
    for (int idx = tid; idx < 16 * DIM_; idx += 256) {
        int i = idx / DIM_, c = idx - i * DIM_;
        int n = (oh * 4 + (i >> 2)) * 56 + (ow * 4 + (i & 3));
        float v = xb[(size_t)n * DIM_ + c];
        sp[i * DIM_ + c] = v;
        xhb[(size_t)n * DIM_ + c] = __float2half_rn(v);
    }
    __syncthreads();
    for (int c = tid; c < DIM_; c += 256) {
        float acc = dwb[c];
#pragma unroll
        for (int i = 0; i < 16; i++)
            acc = fmaf(sp[i * DIM_ + c], dww[c * 16 + i], acc);
        g_dw[(size_t)blockIdx.x * DIM_ + c] = __float2half_rn(acc);
    }
}

// ---------------- weight prep ------------------------------------------------
__global__ void transpose_all(const float* __restrict__ qw, const float* __restrict__ kw,
                              const float* __restrict__ vw, const float* __restrict__ pjw,
                              const float* __restrict__ pww)
{
    int k = blockIdx.x * 256 + threadIdx.x;
    int n = blockIdx.y;
    int which = blockIdx.z;
    if (which == 0) {
        if (k < DIM_ && n < CN_) g_wtq[(size_t)n * DIM_ + k] = __float2half_rn(qw[(size_t)k * CN_ + n]);
    } else if (which == 1) {
        if (k < CN_ && n < CN_)  g_wtkv[(size_t)n * CN_ + k] = __float2half_rn(kw[(size_t)k * CN_ + n]);
    } else if (which == 2) {
        if (k < CN_ && n < DIM_) g_wtkv[(size_t)(400 + n) * CN_ + k] = __float2half_rn(vw[(size_t)k * DIM_ + n]);
    } else if (which == 3) {
        if (k < DIM_ && n < DIM_) g_wtp[(size_t)n * DIM_ + k] = __float2half_rn(pjw[(size_t)k * DIM_ + n]);
    } else {
        if (k < DIM_ && n < CN_) g_wpw[(size_t)n * DIM_ + k] = __float2half_rn(pww[(size_t)n * DIM_ + k]);
    }
}

// ---------------- LN + GELU: g_pre -> g_xs -----------------------------------
__global__ __launch_bounds__(128) void lngelu_kernel(
    const float* __restrict__ lng, const float* __restrict__ lnb)
{
    __shared__ float r1[4], r2[4];
    int r = blockIdx.x, tid = threadIdx.x, lane = tid & 31, w = tid >> 5;
    const float* row = g_pre + (size_t)r * CN_;
    float v[4];
    float s1 = 0.f, s2 = 0.f;
#pragma unroll
    for (int i = 0; i < 4; i++) {
        int c = tid + i * 128;
        v[i] = (c < CN_) ? row[c] : 0.f;
        s1 += v[i]; s2 += v[i] * v[i];
    }
    s1 = warp_sum(s1); s2 = warp_sum(s2);
    if (lane == 0) { r1[w] = s1; r2[w] = s2; }
    __syncthreads();
    float a = r1[0] + r1[1] + r1[2] + r1[3];
    float bq = r2[0] + r2[1] + r2[2] + r2[3];
    float mu = a / (float)CN_;
    float rstd = rsqrtf(bq / (float)CN_ - mu * mu + 1e-5f);
#pragma unroll
    for (int i = 0; i < 4; i++) {
        int c = tid + i * 128;
        if (c < CN_) {
            float y = (v[i] - mu) * rstd * lng[c] + lnb[c];
            float g = 0.5f * y * (1.f + erff(y * 0.70710678118654752f));
            g_xs[(size_t)r * CN_ + c] = __float2half_rn(g);
        }
    }
}

// ---------------- fp16 HMMA GEMM: BM=128, BN=80, BK=64, 3-stage --------------
// Single barrier per iter; load(i+2) issued AFTER the barrier (which proves
// compute(i-1) done by all warps = no readers left in buffer (i+2)%3) and
// BEFORE compute(i), keeping i+1 and i+2 in flight during compute(i).
#define HSTR 72
#define ATILE (128 * HSTR)
#define BTILE (80 * HSTR)
#define STAGEB ((ATILE + BTILE) * 2)
__global__ __launch_bounds__(256, 2) void hgemm(
    const __half* __restrict__ A, const __half* __restrict__ Bt,
    const float* __restrict__ bias, float* __restrict__ Cf,
    __half* __restrict__ Ch, int M, int N, int K)
{
    extern __shared__ __half hsm[];
    uint32_t sbase = smem_u32(hsm);

    int tid = threadIdx.x;
    int lane = tid & 31, w = tid >> 5;
    int g = lane >> 2, t = lane & 3;
    int lrow = lane & 15, lkh = lane >> 4;
    int row0 = blockIdx.x * 128, n0 = blockIdx.y * 80;
    int wm = (w & 3) * 32, wn = (w >> 2) * 40;
    int nIter = (K + 63) / 64;

    float acc[2][5][4] = {};

    auto load_stage = [&](int s, int k0) {
        uint32_t base = sbase + s * STAGEB;
#pragma unroll
        for (int it = 0; it < 4; it++) {
            int gr = tid + it * 256;
            int r = gr >> 3, c8 = (gr & 7) << 3;
            int kk = k0 + c8;
            const __half* sa = A + (size_t)(row0 + r) * K + (kk < K ? kk : 0);
            CPA(base + (r * HSTR + c8) * 2, sa, (kk < K) ? 16 : 0);
        }
#pragma unroll
        for (int it = 0; it < 3; it++) {
            int gr = tid + it * 256;
            if (gr < 640) {
                int r = gr >> 3, c8 = (gr & 7) << 3;
                int kk = k0 + c8;
                const __half* sb = Bt + (size_t)(n0 + r) * K + (kk < K ? kk : 0);
                CPA(base + ATILE * 2 + (r * HSTR + c8) * 2, sb, (kk < K) ? 16 : 0);
            }
        }
        CPC();
    };

    load_stage(0, 0);
    if (nIter > 1) load_stage(1, 64);
    for (int i = 0; i < nIter; i++) {
        if (i + 1 < nIter) CPW(1);   // stage i complete (i+1 may be in flight)
        else CPW(0);
        __syncthreads();             // + all warps done with compute(i-1)

        if (i + 2 < nIter) load_stage((i + 2) % 3, (i + 2) * 64);

        uint32_t sbA = sbase + (i % 3) * STAGEB;
        uint32_t sbB = sbA + ATILE * 2;
#pragma unroll
        for (int ks = 0; ks < 4; ks++) {
            uint32_t af[2][4], q0[4], q1[4], e2[2];
#pragma unroll
            for (int mi = 0; mi < 2; mi++)
                ldsm4(af[mi], sbA + ((wm + mi * 16 + lrow) * HSTR + ks * 16 + lkh * 8) * 2);
            ldsm4(q0, sbB + ((wn + lane) * HSTR + ks * 16 + 0) * 2);
            ldsm4(q1, sbB + ((wn + lane) * HSTR + ks * 16 + 8) * 2);
            ldsm2(e2, sbB + ((wn + 32 + (lane & 7)) * HSTR + ks * 16 + ((lane >> 3) & 1) * 8) * 2);
#pragma unroll
            for (int mi = 0; mi < 2; mi++) {
#pragma unroll
                for (int nj = 0; nj < 4; nj++)
                    mma16(acc[mi][nj], af[mi][0], af[mi][1], af[mi][2], af[mi][3],
                          q0[nj], q1[nj]);
                mma16(acc[mi][4], af[mi][0], af[mi][1], af[mi][2], af[mi][3],
                      e2[0], e2[1]);
            }
        }
    }

#pragma unroll
    for (int mi = 0; mi < 2; mi++)
#pragma unroll
        for (int nj = 0; nj < 5; nj++) {
            int r = row0 + wm + mi * 16 + g;
            int c = n0 + wn + nj * 8 + 2 * t;
            if (Ch) {
                *reinterpret_cast<__half2*>(Ch + (size_t)r * N + c) =
                    __floats2half2_rn(acc[mi][nj][0], acc[mi][nj][1]);
                *reinterpret_cast<__half2*>(Ch + (size_t)(r + 8) * N + c) =
                    __floats2half2_rn(acc[mi][nj][2], acc[mi][nj][3]);
            } else {
                float b0 = bias ? bias[c]     : 0.f;
                float b1 = bias ? bias[c + 1] : 0.f;
                *reinterpret_cast<float2*>(Cf + (size_t)r * N + c) =
                    make_float2(acc[mi][nj][0] + b0, acc[mi][nj][1] + b1);
                *reinterpret_cast<float2*>(Cf + (size_t)(r + 8) * N + c) =
                    make_float2(acc[mi][nj][2] + b0, acc[mi][nj][3] + b1);
            }
        }
}

// ---------------- fused attention (R15: 128 queries, P-in-register split-K) --
#define SQST 88
#define SKST 88
#define SVST 72
#define SOST 68
#define OQ   0
#define OK_  11264
#define OV   30976
#define OF32 47104
#define ATTN_SMEM (OF32 * 2 + (128 * SOST + 512 + 512 + 128) * 4)
__global__ __launch_bounds__(512, 1) void attn_kernel(float scale)
{
    extern __shared__ __half hs[];
    float* sO   = reinterpret_cast<float*>(hs + OF32);
    float* pmax = sO + 128 * SOST;
    float* psum = pmax + 512;
    float* srcp = psum + 512;

    int qt = blockIdx.x, h = blockIdx.y, b = blockIdx.z;
    int q0 = qt * AQ_;
    int tid = threadIdx.x;
    int lane = tid & 31, w = tid >> 5;
    int g = lane >> 2, t = lane & 3;
    int lrow = lane & 15, lkh = lane >> 4;
    int rg = w & 3, wg = w >> 2;
    int mp = rg * 32, nqk = wg * 56;

    for (int i = tid; i < 128 * SOST; i += 512) sO[i] = 0.f;

    {
        const __half* qb = g_q + ((size_t)(b * N_) + q0) * CN_ + h * DQ_;
        for (int idx = tid; idx < AQ_ * 10; idx += 512) {
            int r = idx / 10, c8 = (idx % 10) * 8;
            uint4 v = make_uint4(0, 0, 0, 0);
            if (q0 + r < N_) v = *reinterpret_cast<const uint4*>(qb + (size_t)r * CN_ + c8);
            *reinterpret_cast<uint4*>(hs + OQ + r * SQST + c8) = v;
        }
        const __half* kb = g_kv + (size_t)b * NK_ * 720 + h * DQ_;
        for (int idx = tid; idx < 224 * 10; idx += 512) {
            int j = idx / 10, c8 = (idx % 10) * 8;
            uint4 v = make_uint4(0, 0, 0, 0);
            if (j < NK_) v = *reinterpret_cast<const uint4*>(kb + (size_t)j * 720 + c8);
            *reinterpret_cast<uint4*>(hs + OK_ + j * SKST + c8) = v;
        }
        const __half* vb = g_kv + (size_t)b * NK_ * 720 + 400 + h * DV_;
        for (int idx = tid; idx < 224 * 8; idx += 512) {
            int j = idx / 8, c8 = (idx % 8) * 8;
            uint4 v = make_uint4(0, 0, 0, 0);
            if (j < NK_) v = *reinterpret_cast<const uint4*>(vb + (size_t)j * 720 + c8);
            *reinterpret_cast<uint4*>(hs + OV + j * SVST + c8) = v;
        }
    }
    __syncthreads();

    float acc[2][7][4] = {};
    {
        uint32_t sQb = smem_u32(hs + OQ);
        uint32_t sKb = smem_u32(hs + OK_);
#pragma unroll
        for (int ks = 0; ks < 5; ks++) {
            uint32_t af[2][4];
#pragma unroll
            for (int mi = 0; mi < 2; mi++)
                ldsm4(af[mi], sQb + ((mp + mi * 16 + lrow) * SQST + ks * 16 + lkh * 8) * 2);
            uint32_t bf[7][2];
#pragma unroll
            for (int kh = 0; kh < 2; kh++) {
                uint32_t b4[4], b2[2], b1;
                ldsm4(b4, sKb + ((nqk + lane) * SKST + ks * 16 + kh * 8) * 2);
                ldsm2(b2, sKb + ((nqk + 32 + (lane & 15)) * SKST + ks * 16 + kh * 8) * 2);
                ldsm1(b1, sKb + ((nqk + 48 + (lane & 7)) * SKST + ks * 16 + kh * 8) * 2);
                bf[0][kh] = b4[0]; bf[1][kh] = b4[1]; bf[2][kh] = b4[2]; bf[3][kh] = b4[3];
                bf[4][kh] = b2[0]; bf[5][kh] = b2[1]; bf[6][kh] = b1;
            }
#pragma unroll
            for (int mi = 0; mi < 2; mi++)
#pragma unroll
                for (int nj = 0; nj < 7; nj++)
                    mma16(acc[mi][nj], af[mi][0], af[mi][1], af[mi][2], af[mi][3],
                          bf[nj][0], bf[nj][1]);
        }
    }

#pragma unroll
    for (int mi = 0; mi < 2; mi++) {
        float ma = -1e30f, mb = -1e30f;
#pragma unroll
        for (int nj = 0; nj < 7; nj++) {
            int c = nqk + nj * 8 + 2 * t;
            if (c < NK_) {
                ma = fmaxf(ma, fmaxf(acc[mi][nj][0], acc[mi][nj][1]) * scale);
                mb = fmaxf(mb, fmaxf(acc[mi][nj][2], acc[mi][nj][3]) * scale);
            }
        }
#pragma unroll
        for (int o = 1; o <= 2; o <<= 1) {
            ma = fmaxf(ma, __shfl_xor_sync(0xffffffffu, ma, o));
            mb = fmaxf(mb, __shfl_xor_sync(0xffffffffu, mb, o));
        }
        if (t == 0) {
            pmax[(mp + mi * 16 + g) * 4 + wg]     = ma;
            pmax[(mp + mi * 16 + 8 + g) * 4 + wg] = mb;
        }
    }
    __syncthreads();

#pragma unroll
    for (int mi = 0; mi < 2; mi++) {
        int rA = mp + mi * 16 + g, rB = rA + 8;
        float ma = fmaxf(fmaxf(pmax[rA * 4], pmax[rA * 4 + 1]),
                         fmaxf(pmax[rA * 4 + 2], pmax[rA * 4 + 3]));
        float mb = fmaxf(fmaxf(pmax[rB * 4], pmax[rB * 4 + 1]),
                         fmaxf(pmax[rB * 4 + 2], pmax[rB * 4 + 3]));
        float sa = 0.f, sb = 0.f;
#pragma unroll
        for (int nj = 0; nj < 7; nj++) {
            int c = nqk + nj * 8 + 2 * t;
            if (c < NK_) {
                float e0 = __expf(acc[mi][nj][0] * scale - ma);
                float e1 = __expf(acc[mi][nj][1] * scale - ma);
                float e2 = __expf(acc[mi][nj][2] * scale - mb);
                float e3 = __expf(acc[mi][nj][3] * scale - mb);
                acc[mi][nj][0] = e0; acc[mi][nj][1] = e1;
                acc[mi][nj][2] = e2; acc[mi][nj][3] = e3;
                sa += e0 + e1; sb += e2 + e3;
            } else {
                acc[mi][nj][0] = acc[mi][nj][1] = 0.f;
                acc[mi][nj][2] = acc[mi][nj][3] = 0.f;
            }
        }
#pragma unroll
        for (int o = 1; o <= 2; o <<= 1) {
            sa += __shfl_xor_sync(0xffffffffu, sa, o);
            sb += __shfl_xor_sync(0xffffffffu, sb, o);
        }
        if (t == 0) { psum[rA * 4 + wg] = sa; psum[rB * 4 + wg] = sb; }
    }

    uint32_t ppa[2][7], ppb[2][7];
#pragma unroll
    for (int mi = 0; mi < 2; mi++)
#pragma unroll
        for (int nj = 0; nj < 7; nj++) {
            ppa[mi][nj] = packh2(acc[mi][nj][0], acc[mi][nj][1]);
            ppb[mi][nj] = packh2(acc[mi][nj][2], acc[mi][nj][3]);
        }
    __syncthreads();

    if (tid < AQ_)
        srcp[tid] = 1.f / (psum[tid * 4] + psum[tid * 4 + 1] +
                           psum[tid * 4 + 2] + psum[tid * 4 + 3]);

    {
        uint32_t sVb = smem_u32(hs + OV);
#pragma unroll
        for (int vh = 0; vh < 2; vh++) {
            float o[2][4][4] = {};
#pragma unroll
            for (int ks = 0; ks < 7; ks++) {
                uint32_t bt[4];
                ldsm4t(bt, sVb + ((nqk + ks * 8 + (lane & 7)) * SVST
                                  + vh * 32 + (lane >> 3) * 8) * 2);
#pragma unroll
                for (int mi = 0; mi < 2; mi++)
#pragma unroll
                    for (int nj = 0; nj < 4; nj++)
                        mma8k(o[mi][nj], ppa[mi][ks], ppb[mi][ks], bt[nj]);
            }
#pragma unroll
            for (int mi = 0; mi < 2; mi++)
#pragma unroll
                for (int nj = 0; nj < 4; nj++) {
                    int row = mp + mi * 16 + g;
                    int col = vh * 32 + nj * 8 + 2 * t;
                    atomicAdd(&sO[row * SOST + col],           o[mi][nj][0]);
                    atomicAdd(&sO[row * SOST + col + 1],       o[mi][nj][1]);
                    atomicAdd(&sO[(row + 8) * SOST + col],     o[mi][nj][2]);
                    atomicAdd(&sO[(row + 8) * SOST + col + 1], o[mi][nj][3]);
                }
        }
    }
    __syncthreads();

    for (int idx = tid; idx < AQ_ * 32; idx += 512) {
        int r = idx >> 5, c2 = idx & 31;
        if (q0 + r < N_) {
            float rc = srcp[r];
            float o0 = sO[r * SOST + 2 * c2]     * rc;
            float o1 = sO[r * SOST + 2 * c2 + 1] * rc;
            *reinterpret_cast<__half2*>(
                g_av + ((size_t)(b * N_) + q0 + r) * DIM_ + h * DV_ + 2 * c2) =
                __floats2half2_rn(o0, o1);
        }
    }
}

// ---------------- launch -----------------------------------------------------
extern "C" void kernel_launch(void* const* d_in, const int* in_sizes, int n_in,
                              void* d_out, int out_size)
{
    const float* x   = (const float*)d_in[0];
    const float* dww = (const float*)d_in[3];
    const float* dwb = (const float*)d_in[4];
    const float* pww = (const float*)d_in[5];
    const float* pwb = (const float*)d_in[6];
    const float* lng = (const float*)d_in[7];
    const float* lnb = (const float*)d_in[8];
    const float* qw  = (const float*)d_in[9];
    const float* kw  = (const float*)d_in[10];
    const float* vw  = (const float*)d_in[11];
    const float* pjw = (const float*)d_in[12];
    const float* pjb = (const float*)d_in[13];
    float* out = (float*)d_out;

    __half *pxh, *pdw, *pxs, *pq, *pkv, *pav, *pwtq, *pwtkv, *pwtp, *pwpw;
    float *ppre;
    cudaGetSymbolAddress((void**)&pxh,   g_xh);
    cudaGetSymbolAddress((void**)&pdw,   g_dw);
    cudaGetSymbolAddress((void**)&ppre,  g_pre);
    cudaGetSymbolAddress((void**)&pxs,   g_xs);
    cudaGetSymbolAddress((void**)&pq,    g_q);
    cudaGetSymbolAddress((void**)&pkv,   g_kv);
    cudaGetSymbolAddress((void**)&pav,   g_av);
    cudaGetSymbolAddress((void**)&pwtq,  g_wtq);
    cudaGetSymbolAddress((void**)&pwtkv, g_wtkv);
    cudaGetSymbolAddress((void**)&pwtp,  g_wtp);
    cudaGetSymbolAddress((void**)&pwpw,  g_wpw);

    dwcvt_kernel<<<B_ * NK_, 256>>>(x, dww, dwb);
    transpose_all<<<dim3(2, CN_, 5), 256>>>(qw, kw, vw, pjw, pww);

    const int gemm_smem = 3 * STAGEB;   // 89856 B
    cudaFuncSetAttribute(hgemm, cudaFuncAttributeMaxDynamicSharedMemorySize, gemm_smem);

    // pointwise conv as GEMM
    hgemm<<<dim3(B_ * NK_ / 128, CN_ / 80), 256, gemm_smem>>>(
        pdw, pwpw, pwb, ppre, nullptr, B_ * NK_, CN_, DIM_);

    lngelu_kernel<<<B_ * NK_, 128>>>(lng, lnb);

    // q = x @ q_w
    hgemm<<<dim3(B_ * N_ / 128, CN_ / 80), 256, gemm_smem>>>(
        pxh, pwtq, nullptr, nullptr, pq, B_ * N_, CN_, DIM_);

    // kv = xs @ [k_w | v_w]
    hgemm<<<dim3(B_ * NK_ / 128, 720 / 80), 256, gemm_smem>>>(
        pxs, pwtkv, nullptr, nullptr, pkv, B_ * NK_, 720, CN_);

    cudaFuncSetAttribute(attn_kernel,
                         cudaFuncAttributeMaxDynamicSharedMemorySize, ATTN_SMEM);
    attn_kernel<<<dim3((N_ + AQ_ - 1) / AQ_, HEADS_, B_), 512, ATTN_SMEM>>>(
        0.11180339887498949f /* 80^-0.5 */);

    // out = av @ proj_w + proj_b
    hgemm<<<dim3(B_ * N_ / 128, DIM_ / 80), 256, gemm_smem>>>(
        pav, pwtp, pjb, out, nullptr, B_ * N_, DIM_, DIM_);
}